// round 13
// baseline (speedup 1.0000x reference)
#include <cuda_runtime.h>
#include <cuda_fp16.h>
#include <cstdint>

#define D    128
#define HS   136           // smem row stride in halves: 68 words ≡ 4 mod 32 → conflict-free
#define MAXN 100000
#define CAP  64            // bucket capacity per node (Poisson(16) tail: safe)

// ---------------- scratch (__device__ globals, allocation-free) -------------
__device__ __half   g_h[(size_t)MAXN * D];       // x @ W^T, fp16
__device__ int      g_cnt[MAXN];
__device__ int      g_bkt[(size_t)MAXN * CAP];   // bucketed adjacency (src ids)

// ---------------------------------------------------------------------------
__device__ __forceinline__ void mma_f16(float* c, uint32_t a0, uint32_t a1,
                                        uint32_t a2, uint32_t a3,
                                        uint32_t b0, uint32_t b1) {
    asm volatile(
        "mma.sync.aligned.m16n8k16.row.col.f32.f16.f16.f32 "
        "{%0,%1,%2,%3}, {%4,%5,%6,%7}, {%8,%9}, {%0,%1,%2,%3};"
        : "+f"(c[0]), "+f"(c[1]), "+f"(c[2]), "+f"(c[3])
        : "r"(a0), "r"(a1), "r"(a2), "r"(a3), "r"(b0), "r"(b1));
}

__device__ __forceinline__ void ldsm4(uint32_t& r0, uint32_t& r1, uint32_t& r2,
                                      uint32_t& r3, uint32_t addr) {
    asm volatile("ldmatrix.sync.aligned.m8n8.x4.shared.b16 {%0,%1,%2,%3}, [%4];"
                 : "=r"(r0), "=r"(r1), "=r"(r2), "=r"(r3) : "r"(addr));
}

// ---------------------------------------------------------------------------
// 1) zero degree counts
// ---------------------------------------------------------------------------
__global__ void k_pre(int n) {
    int i = blockIdx.x * blockDim.x + threadIdx.x;
    if (i < n) g_cnt[i] = 0;
}

// ---------------------------------------------------------------------------
// 2) FUSED: gemm blocks (1 in 5) + fillb blocks (4 in 5), interleaved so the
//    DRAM/tensor-bound GEMM overlaps the L2-atomic-bound adjacency build.
// ---------------------------------------------------------------------------
__launch_bounds__(512)
__global__ void k_fused(const float* __restrict__ x, const float* __restrict__ W,
                        const int* __restrict__ src, const int* __restrict__ dst,
                        int n, int e, int nGemm) {
    int bid = blockIdx.x;
    int q = bid / 5, r = bid % 5;
    bool isGemm = (r == 4) && (q < nGemm);

    if (!isGemm) {
        // ---------------- fillb ----------------
        int gBefore = (q < nGemm) ? q : nGemm;
        int fillId = bid - gBefore;
        int i = fillId * 512 + threadIdx.x;
        if (i < e) {
            int d = dst[i];
            int c = atomicAdd(&g_cnt[d], 1);
            if (c < CAP) g_bkt[(size_t)d * CAP + c] = src[i];
        }
        return;
    }

    // ---------------- GEMM: h = x @ W^T, fp16 mma m16n8k16 ----------------
    extern __shared__ __half smem_h[];
    __half* xs = smem_h;              // 128 * HS halves
    __half* ws = smem_h + 128 * HS;   // 128 * HS halves

    int tid  = threadIdx.x;
    int row0 = q * 128;

    #pragma unroll
    for (int it = 0; it < 8; it++) {
        int i4 = tid + it * 512;        // 0..4095
        int rr = i4 >> 5, qq = i4 & 31;
        float4 v = make_float4(0.f, 0.f, 0.f, 0.f);
        if (row0 + rr < n) v = *(const float4*)(x + (size_t)(row0 + rr) * D + qq * 4);
        *(__half2*)(xs + rr * HS + qq * 4)     = __floats2half2_rn(v.x, v.y);
        *(__half2*)(xs + rr * HS + qq * 4 + 2) = __floats2half2_rn(v.z, v.w);
        float4 w = *(const float4*)(W + (size_t)rr * D + qq * 4);
        *(__half2*)(ws + rr * HS + qq * 4)     = __floats2half2_rn(w.x, w.y);
        *(__half2*)(ws + rr * HS + qq * 4 + 2) = __floats2half2_rn(w.z, w.w);
    }
    __syncthreads();

    int lane = tid & 31;
    int wid  = tid >> 5;
    int t4 = lane >> 2;       // 0..7
    int tm = lane & 3;        // 0..3
    int warpRow = (wid & 7) * 16;
    int warpCol = (wid >> 3) * 64;

    float acc[8][4];
    #pragma unroll
    for (int nt = 0; nt < 8; nt++)
        #pragma unroll
        for (int i = 0; i < 4; i++) acc[nt][i] = 0.0f;

    // ldmatrix base addresses (byte, shared space)
    uint32_t xs_b = (uint32_t)__cvta_generic_to_shared(xs);
    uint32_t ws_b = (uint32_t)__cvta_generic_to_shared(ws);
    // A: lanes 0-15 -> rows (k0), lanes 16-31 -> rows (k0+8)
    uint32_t aAddr = xs_b + (((warpRow + (lane & 15)) * HS + ((lane >> 4) << 3)) << 1);
    // B pair p: lanes 0-7 rows p*16+0..7 k0 | 8-15 same rows k8 | 16-23 rows+8 k0 | 24-31 rows+8 k8
    uint32_t bRow = warpCol + ((lane >> 4) << 3) + (lane & 7);
    uint32_t bK   = ((lane >> 3) & 1) << 3;
    uint32_t bAddr0 = ws_b + (((bRow)      * HS + bK) << 1);
    uint32_t bAddr1 = ws_b + (((bRow + 16) * HS + bK) << 1);
    uint32_t bAddr2 = ws_b + (((bRow + 32) * HS + bK) << 1);
    uint32_t bAddr3 = ws_b + (((bRow + 48) * HS + bK) << 1);

    #pragma unroll
    for (int kc = 0; kc < 8; kc++) {
        uint32_t koff = (kc * 16) << 1;
        uint32_t a0, a1, a2, a3;
        ldsm4(a0, a1, a2, a3, aAddr + koff);
        uint32_t b[16];
        ldsm4(b[0],  b[1],  b[2],  b[3],  bAddr0 + koff);
        ldsm4(b[4],  b[5],  b[6],  b[7],  bAddr1 + koff);
        ldsm4(b[8],  b[9],  b[10], b[11], bAddr2 + koff);
        ldsm4(b[12], b[13], b[14], b[15], bAddr3 + koff);
        #pragma unroll
        for (int nt = 0; nt < 8; nt++)
            mma_f16(acc[nt], a0, a1, a2, a3, b[nt * 2], b[nt * 2 + 1]);
    }

    int r1 = row0 + warpRow + t4;
    int r2 = r1 + 8;
    #pragma unroll
    for (int nt = 0; nt < 8; nt++) {
        int n0 = warpCol + nt * 8 + 2 * tm;
        if (r1 < n) *(__half2*)(g_h + (size_t)r1 * D + n0) =
            __floats2half2_rn(acc[nt][0], acc[nt][1]);
        if (r2 < n) *(__half2*)(g_h + (size_t)r2 * D + n0) =
            __floats2half2_rn(acc[nt][2], acc[nt][3]);
    }
}

// ---------------------------------------------------------------------------
// 3) gather-aggregate: warp/node, x4 unrolled (MLP=4), fp16 h gather,
//    on-the-fly rsqrt dinv, fused self-loop + bias + PReLU
// ---------------------------------------------------------------------------
__device__ __forceinline__ void unpack_fma(uint2 u, float nm,
                                           float& ax, float& ay, float& az, float& aw) {
    float2 f0 = __half22float2(*(__half2*)&u.x);
    float2 f1 = __half22float2(*(__half2*)&u.y);
    ax += f0.x * nm; ay += f0.y * nm;
    az += f1.x * nm; aw += f1.y * nm;
}

__launch_bounds__(256)
__global__ void k_agg(const float* __restrict__ b, const float* __restrict__ a,
                      float* __restrict__ out, int n) {
    int node = (blockIdx.x * blockDim.x + threadIdx.x) >> 5;
    int lane = threadIdx.x & 31;
    if (node >= n) return;

    const uint2* hb = (const uint2*)g_h;    // 32 uint2 per row
    const int* bkt = g_bkt + (size_t)node * CAP;
    int cntRaw = g_cnt[node];
    float dd = rsqrtf((float)cntRaw + 1.0f);
    float self = dd * dd;

    float ax = 0.f, ay = 0.f, az = 0.f, aw = 0.f;
    unpack_fma(__ldg(hb + (size_t)node * 32 + lane), self, ax, ay, az, aw);

    int cnt = cntRaw > CAP ? CAP : cntRaw;
    int j = 0;

    for (; j + 4 <= cnt; j += 4) {
        int s0 = __ldg(bkt + j);
        int s1 = __ldg(bkt + j + 1);
        int s2 = __ldg(bkt + j + 2);
        int s3 = __ldg(bkt + j + 3);
        uint2 v0 = __ldg(hb + (size_t)s0 * 32 + lane);
        uint2 v1 = __ldg(hb + (size_t)s1 * 32 + lane);
        uint2 v2 = __ldg(hb + (size_t)s2 * 32 + lane);
        uint2 v3 = __ldg(hb + (size_t)s3 * 32 + lane);
        float n0 = rsqrtf((float)__ldg(g_cnt + s0) + 1.0f) * dd;
        float n1 = rsqrtf((float)__ldg(g_cnt + s1) + 1.0f) * dd;
        float n2 = rsqrtf((float)__ldg(g_cnt + s2) + 1.0f) * dd;
        float n3 = rsqrtf((float)__ldg(g_cnt + s3) + 1.0f) * dd;
        unpack_fma(v0, n0, ax, ay, az, aw);
        unpack_fma(v1, n1, ax, ay, az, aw);
        unpack_fma(v2, n2, ax, ay, az, aw);
        unpack_fma(v3, n3, ax, ay, az, aw);
    }
    for (; j < cnt; j++) {
        int s0 = __ldg(bkt + j);
        uint2 v0 = __ldg(hb + (size_t)s0 * 32 + lane);
        float n0 = rsqrtf((float)__ldg(g_cnt + s0) + 1.0f) * dd;
        unpack_fma(v0, n0, ax, ay, az, aw);
    }

    float4 bv = ((const float4*)b)[lane];
    ax += bv.x; ay += bv.y; az += bv.z; aw += bv.w;

    float slope = a[0];
    ax = ax >= 0.f ? ax : slope * ax;
    ay = ay >= 0.f ? ay : slope * ay;
    az = az >= 0.f ? az : slope * az;
    aw = aw >= 0.f ? aw : slope * aw;

    ((float4*)(out + (size_t)node * D))[lane] = make_float4(ax, ay, az, aw);
}

// ---------------------------------------------------------------------------
extern "C" void kernel_launch(void* const* d_in, const int* in_sizes, int n_in,
                              void* d_out, int out_size) {
    const float* x  = (const float*)d_in[0];
    const int*   ei = (const int*)d_in[1];
    const float* W  = (const float*)d_in[2];
    const float* b  = (const float*)d_in[3];
    const float* a  = (const float*)d_in[4];
    float* out = (float*)d_out;

    int n = in_sizes[0] / D;
    int e = in_sizes[1] / 2;
    const int* src = ei;
    const int* dst = ei + e;

    int nb = (n + 255) / 256;
    int nGemm = (n + 127) / 128;
    int nFill = (e + 511) / 512;
    int total = nGemm * 5;
    if (total < nGemm + nFill) total = nGemm + nFill;

    k_pre<<<nb, 256>>>(n);

    const int fused_smem = 2 * 128 * HS * 2;   // 69632 B
    cudaFuncSetAttribute(k_fused, cudaFuncAttributeMaxDynamicSharedMemorySize, fused_smem);
    k_fused<<<total, 512, fused_smem>>>(x, W, src, dst, n, e, nGemm);

    k_agg<<<(n * 32 + 255) / 256, 256>>>(b, a, out, n);
}

// round 14
// speedup vs baseline: 1.0400x; 1.0400x over previous
#include <cuda_runtime.h>
#include <cuda_fp16.h>
#include <cstdint>

#define D    128
#define HS   136           // smem row stride in halves: 68 words ≡ 4 mod 32 → conflict-free
#define MAXN 100000
#define CAP  64            // bucket capacity per node (Poisson(16) tail: safe)

// ---------------- scratch (__device__ globals, allocation-free) -------------
// g_cnt is zero at module load (.bss) and re-zeroed by k_dinv every call:
// the "counts are zero at kernel_launch entry" invariant holds on every run.
__device__ __half   g_h[(size_t)MAXN * D];       // x @ W^T, fp16
__device__ int      g_cnt[MAXN];                 // transient edge counters
__device__ int      g_deg[MAXN];                 // snapshotted degree
__device__ float    g_dinv[MAXN];                // rsqrt(deg+1)
__device__ int      g_bkt[(size_t)MAXN * CAP];   // bucketed adjacency (src ids)

// ---------------------------------------------------------------------------
__device__ __forceinline__ void mma_f16(float* c, uint32_t a0, uint32_t a1,
                                        uint32_t a2, uint32_t a3,
                                        uint32_t b0, uint32_t b1) {
    asm volatile(
        "mma.sync.aligned.m16n8k16.row.col.f32.f16.f16.f32 "
        "{%0,%1,%2,%3}, {%4,%5,%6,%7}, {%8,%9}, {%0,%1,%2,%3};"
        : "+f"(c[0]), "+f"(c[1]), "+f"(c[2]), "+f"(c[3])
        : "r"(a0), "r"(a1), "r"(a2), "r"(a3), "r"(b0), "r"(b1));
}

__device__ __forceinline__ void ldsm4(uint32_t& r0, uint32_t& r1, uint32_t& r2,
                                      uint32_t& r3, uint32_t addr) {
    asm volatile("ldmatrix.sync.aligned.m8n8.x4.shared.b16 {%0,%1,%2,%3}, [%4];"
                 : "=r"(r0), "=r"(r1), "=r"(r2), "=r"(r3) : "r"(addr));
}

// ---------------------------------------------------------------------------
// 1) single-pass bucketed adjacency build (g_cnt starts zero by invariant)
// ---------------------------------------------------------------------------
__global__ void k_fillb(const int* __restrict__ src, const int* __restrict__ dst, int e) {
    int i = blockIdx.x * blockDim.x + threadIdx.x;
    if (i < e) {
        int d = dst[i];
        int c = atomicAdd(&g_cnt[d], 1);
        if (c < CAP) g_bkt[(size_t)d * CAP + c] = src[i];
    }
}

// 2) snapshot degree, compute dinv, restore the g_cnt == 0 invariant
__global__ void k_dinv(int n) {
    int i = blockIdx.x * blockDim.x + threadIdx.x;
    if (i < n) {
        int c = g_cnt[i];
        g_deg[i]  = c > CAP ? CAP : c;
        g_dinv[i] = rsqrtf((float)c + 1.0f);   // +1 self loop
        g_cnt[i]  = 0;
    }
}

// ---------------------------------------------------------------------------
// 3) GEMM: h = x @ W^T via fp16 mma m16n8k16, ldmatrix fragments.
//    Block 512 thr (16 warps), tile 128x128, full K resident in smem.
// ---------------------------------------------------------------------------
__launch_bounds__(512)
__global__ void k_gemm(const float* __restrict__ x, const float* __restrict__ W, int n) {
    extern __shared__ __half smem_h[];
    __half* xs = smem_h;              // 128 * HS halves
    __half* ws = smem_h + 128 * HS;   // 128 * HS halves

    int tid  = threadIdx.x;
    int row0 = blockIdx.x * 128;

    #pragma unroll
    for (int it = 0; it < 8; it++) {
        int i4 = tid + it * 512;        // 0..4095
        int rr = i4 >> 5, qq = i4 & 31;
        float4 v = make_float4(0.f, 0.f, 0.f, 0.f);
        if (row0 + rr < n) v = *(const float4*)(x + (size_t)(row0 + rr) * D + qq * 4);
        *(__half2*)(xs + rr * HS + qq * 4)     = __floats2half2_rn(v.x, v.y);
        *(__half2*)(xs + rr * HS + qq * 4 + 2) = __floats2half2_rn(v.z, v.w);
        float4 w = *(const float4*)(W + (size_t)rr * D + qq * 4);
        *(__half2*)(ws + rr * HS + qq * 4)     = __floats2half2_rn(w.x, w.y);
        *(__half2*)(ws + rr * HS + qq * 4 + 2) = __floats2half2_rn(w.z, w.w);
    }
    __syncthreads();

    int lane = tid & 31;
    int wid  = tid >> 5;
    int t4 = lane >> 2;       // 0..7
    int tm = lane & 3;        // 0..3
    int warpRow = (wid & 7) * 16;
    int warpCol = (wid >> 3) * 64;

    float acc[8][4];
    #pragma unroll
    for (int nt = 0; nt < 8; nt++)
        #pragma unroll
        for (int i = 0; i < 4; i++) acc[nt][i] = 0.0f;

    uint32_t xs_b = (uint32_t)__cvta_generic_to_shared(xs);
    uint32_t ws_b = (uint32_t)__cvta_generic_to_shared(ws);
    uint32_t aAddr = xs_b + (((warpRow + (lane & 15)) * HS + ((lane >> 4) << 3)) << 1);
    uint32_t bRow = warpCol + ((lane >> 4) << 3) + (lane & 7);
    uint32_t bK   = ((lane >> 3) & 1) << 3;
    uint32_t bAddr0 = ws_b + (((bRow)      * HS + bK) << 1);
    uint32_t bAddr1 = ws_b + (((bRow + 16) * HS + bK) << 1);
    uint32_t bAddr2 = ws_b + (((bRow + 32) * HS + bK) << 1);
    uint32_t bAddr3 = ws_b + (((bRow + 48) * HS + bK) << 1);

    #pragma unroll
    for (int kc = 0; kc < 8; kc++) {
        uint32_t koff = (kc * 16) << 1;
        uint32_t a0, a1, a2, a3;
        ldsm4(a0, a1, a2, a3, aAddr + koff);
        uint32_t b[16];
        ldsm4(b[0],  b[1],  b[2],  b[3],  bAddr0 + koff);
        ldsm4(b[4],  b[5],  b[6],  b[7],  bAddr1 + koff);
        ldsm4(b[8],  b[9],  b[10], b[11], bAddr2 + koff);
        ldsm4(b[12], b[13], b[14], b[15], bAddr3 + koff);
        #pragma unroll
        for (int nt = 0; nt < 8; nt++)
            mma_f16(acc[nt], a0, a1, a2, a3, b[nt * 2], b[nt * 2 + 1]);
    }

    int r1 = row0 + warpRow + t4;
    int r2 = r1 + 8;
    #pragma unroll
    for (int nt = 0; nt < 8; nt++) {
        int n0 = warpCol + nt * 8 + 2 * tm;
        if (r1 < n) *(__half2*)(g_h + (size_t)r1 * D + n0) =
            __floats2half2_rn(acc[nt][0], acc[nt][1]);
        if (r2 < n) *(__half2*)(g_h + (size_t)r2 * D + n0) =
            __floats2half2_rn(acc[nt][2], acc[nt][3]);
    }
}

// ---------------------------------------------------------------------------
// 4) gather-aggregate: warp/node, x4 unrolled (MLP=4), fp16 h gather,
//    fused self-loop + bias + PReLU
// ---------------------------------------------------------------------------
__device__ __forceinline__ void unpack_fma(uint2 u, float nm,
                                           float& ax, float& ay, float& az, float& aw) {
    float2 f0 = __half22float2(*(__half2*)&u.x);
    float2 f1 = __half22float2(*(__half2*)&u.y);
    ax += f0.x * nm; ay += f0.y * nm;
    az += f1.x * nm; aw += f1.y * nm;
}

__launch_bounds__(256)
__global__ void k_agg(const float* __restrict__ b, const float* __restrict__ a,
                      float* __restrict__ out, int n) {
    int node = (blockIdx.x * blockDim.x + threadIdx.x) >> 5;
    int lane = threadIdx.x & 31;
    if (node >= n) return;

    const uint2* hb = (const uint2*)g_h;    // 32 uint2 per row
    const int* bkt = g_bkt + (size_t)node * CAP;
    float dd = g_dinv[node];
    float self = dd * dd;

    float ax = 0.f, ay = 0.f, az = 0.f, aw = 0.f;
    unpack_fma(__ldg(hb + (size_t)node * 32 + lane), self, ax, ay, az, aw);

    int cnt = g_deg[node];
    int j = 0;

    for (; j + 4 <= cnt; j += 4) {
        int s0 = __ldg(bkt + j);
        int s1 = __ldg(bkt + j + 1);
        int s2 = __ldg(bkt + j + 2);
        int s3 = __ldg(bkt + j + 3);
        uint2 v0 = __ldg(hb + (size_t)s0 * 32 + lane);
        uint2 v1 = __ldg(hb + (size_t)s1 * 32 + lane);
        uint2 v2 = __ldg(hb + (size_t)s2 * 32 + lane);
        uint2 v3 = __ldg(hb + (size_t)s3 * 32 + lane);
        float n0 = __ldg(g_dinv + s0) * dd;
        float n1 = __ldg(g_dinv + s1) * dd;
        float n2 = __ldg(g_dinv + s2) * dd;
        float n3 = __ldg(g_dinv + s3) * dd;
        unpack_fma(v0, n0, ax, ay, az, aw);
        unpack_fma(v1, n1, ax, ay, az, aw);
        unpack_fma(v2, n2, ax, ay, az, aw);
        unpack_fma(v3, n3, ax, ay, az, aw);
    }
    for (; j < cnt; j++) {
        int s0 = __ldg(bkt + j);
        uint2 v0 = __ldg(hb + (size_t)s0 * 32 + lane);
        float n0 = __ldg(g_dinv + s0) * dd;
        unpack_fma(v0, n0, ax, ay, az, aw);
    }

    float4 bv = ((const float4*)b)[lane];
    ax += bv.x; ay += bv.y; az += bv.z; aw += bv.w;

    float slope = a[0];
    ax = ax >= 0.f ? ax : slope * ax;
    ay = ay >= 0.f ? ay : slope * ay;
    az = az >= 0.f ? az : slope * az;
    aw = aw >= 0.f ? aw : slope * aw;

    ((float4*)(out + (size_t)node * D))[lane] = make_float4(ax, ay, az, aw);
}

// ---------------------------------------------------------------------------
extern "C" void kernel_launch(void* const* d_in, const int* in_sizes, int n_in,
                              void* d_out, int out_size) {
    const float* x  = (const float*)d_in[0];
    const int*   ei = (const int*)d_in[1];
    const float* W  = (const float*)d_in[2];
    const float* b  = (const float*)d_in[3];
    const float* a  = (const float*)d_in[4];
    float* out = (float*)d_out;

    int n = in_sizes[0] / D;
    int e = in_sizes[1] / 2;
    const int* src = ei;
    const int* dst = ei + e;

    int nb = (n + 255) / 256;
    int eb = (e + 255) / 256;

    k_fillb<<<eb, 256>>>(src, dst, e);
    k_dinv<<<nb, 256>>>(n);

    const int gemm_smem = 2 * 128 * HS * 2;   // 69632 B
    cudaFuncSetAttribute(k_gemm, cudaFuncAttributeMaxDynamicSharedMemorySize, gemm_smem);
    k_gemm<<<(n + 127) / 128, 512, gemm_smem>>>(x, W, n);

    k_agg<<<(n * 32 + 255) / 256, 256>>>(b, a, out, n);
}